// round 9
// baseline (speedup 1.0000x reference)
#include <cuda_runtime.h>
#include <cuda_fp16.h>

#define Bsz 16
#define Nn  740
#define Hh  16
#define HD  32
#define Cc  512
#define N3  1536
#define Mrows (Bsz*Nn)            // 11840
#define SCALE 0.1767766952966369f // 1/sqrt(32)
#define VROW 744                  // padded g_vT row (16B-aligned)

// ---------------- static device scratch (no allocations allowed) ----------
__device__ __align__(128) __half g_xh [(size_t)Mrows*Cc];
__device__ __align__(128) __half g_wqh[(size_t)Cc*N3];
__device__ __align__(128) __half g_wph[(size_t)Cc*Cc];
__device__ __align__(128) __half g_q  [(size_t)Bsz*Hh*Nn*HD + 64];
__device__ __align__(128) __half g_k  [(size_t)Bsz*Hh*Nn*HD + 32768]; // + tail pad
__device__ __align__(128) __half g_vT [(size_t)Bsz*Hh*HD*VROW + 1024];
__device__ __align__(128) __half g_ao [(size_t)Mrows*Cc];
__device__ __align__(128) __half g_biash[(size_t)Hh*Nn*Nn + 64];   // fp16 bias

// ---------------- helpers --------------------------------------------------
__device__ __forceinline__ void mma16816(float* c, const unsigned* a,
                                         unsigned b0, unsigned b1) {
    asm volatile(
        "mma.sync.aligned.m16n8k16.row.col.f32.f16.f16.f32 "
        "{%0,%1,%2,%3}, {%4,%5,%6,%7}, {%8,%9}, {%0,%1,%2,%3};\n"
        : "+f"(c[0]), "+f"(c[1]), "+f"(c[2]), "+f"(c[3])
        : "r"(a[0]), "r"(a[1]), "r"(a[2]), "r"(a[3]), "r"(b0), "r"(b1));
}
__device__ __forceinline__ void ldsm4(unsigned* r, unsigned addr) {
    asm volatile("ldmatrix.sync.aligned.m8n8.x4.shared.b16 {%0,%1,%2,%3}, [%4];\n"
                 : "=r"(r[0]), "=r"(r[1]), "=r"(r[2]), "=r"(r[3]) : "r"(addr));
}
__device__ __forceinline__ void ldsm4t(unsigned* r, unsigned addr) {
    asm volatile("ldmatrix.sync.aligned.m8n8.x4.trans.shared.b16 {%0,%1,%2,%3}, [%4];\n"
                 : "=r"(r[0]), "=r"(r[1]), "=r"(r[2]), "=r"(r[3]) : "r"(addr));
}
__device__ __forceinline__ void cpasync16(void* sdst, const void* gsrc) {
    unsigned sa = (unsigned)__cvta_generic_to_shared(sdst);
    asm volatile("cp.async.cg.shared.global [%0], [%1], 16;\n" :: "r"(sa), "l"(gsrc));
}
#define CP_COMMIT() asm volatile("cp.async.commit_group;\n")
#define CP_WAIT(N)  asm volatile("cp.async.wait_group %0;\n" :: "n"(N))
__device__ __forceinline__ unsigned h2u(__half2 h) { return *(unsigned*)&h; }

// GEMM stage sizes in halves: A [128][40], B [32][136]
#define A_STG (128*40)
#define B_STG (32*136)
#define SMEM_GEMM (3*(A_STG + B_STG)*2)

// ===========================================================================
// fp32 -> fp16 conversion of x, W_qkv, W_proj
// ===========================================================================
__global__ __launch_bounds__(256) void conv_kernel(
    const float* __restrict__ x, const float* __restrict__ wq,
    const float* __restrict__ wp)
{
    const int XN = Mrows*Cc/4, QN = Cc*N3/4, PN = Cc*Cc/4;
    const int total = XN + QN + PN;
    const int stride = gridDim.x * blockDim.x;
    for (int i = blockIdx.x*blockDim.x + threadIdx.x; i < total; i += stride) {
        const float4* src; __half* dst; int j = i;
        if (j < XN)           { src = (const float4*)x;  dst = g_xh; }
        else if (j < XN + QN) { j -= XN; src = (const float4*)wq; dst = g_wqh; }
        else                  { j -= XN + QN; src = (const float4*)wp; dst = g_wph; }
        float4 f = src[j];
        __half2 h0 = __floats2half2_rn(f.x, f.y);
        __half2 h1 = __floats2half2_rn(f.z, f.w);
        *(uint2*)&dst[(size_t)j*4] = make_uint2(h2u(h0), h2u(h1));
    }
}

// ===========================================================================
// Bias precompute: g_biash[h][i][j] (fp16 — halves L2 traffic in attn)
// ===========================================================================
__global__ __launch_bounds__(256) void bias_kernel(
    const float* __restrict__ bt_target, const float* __restrict__ bt_temp,
    const float* __restrict__ tmp_tgt_tab, const float* __restrict__ tgt_tmp_tab,
    const float* __restrict__ tmp_tgt_line, const float* __restrict__ tgt_tmp_line)
{
    const int i = blockIdx.x, h = blockIdx.y;
    const bool tmpR = i < 256;
    int r0, r1; float rowline;
    if (tmpR) { r0 = i >> 4; r1 = i & 15; rowline = tgt_tmp_tab[h*256 + i]; }
    else      { int a = i - 256; r0 = a/22; r1 = a%22; rowline = tmp_tgt_tab[h*484 + a]; }
    __half* dst = g_biash + ((size_t)h*Nn + i)*Nn;
    for (int j = threadIdx.x; j < Nn; j += 256) {
        float bv;
        if (j < 256) {
            if (tmpR) {
                int idx = (r0 - (j >> 4) + 15)*31 + (r1 - (j & 15) + 15);
                bv = bt_temp[idx*Hh + h];
            } else bv = rowline + tmp_tgt_line[h*256 + j];
        } else {
            int cc = j - 256;
            if (tmpR) bv = rowline + tgt_tmp_line[h*484 + cc];
            else {
                int idx = (r0 - cc/22 + 21)*43 + (r1 - cc%22 + 21);
                bv = bt_target[idx*Hh + h];
            }
        }
        dst[j] = __float2half(bv);
    }
}

// ===========================================================================
// QKV GEMM (fp16 mma + ldmatrix + 3-stage cp.async): x_h @ Wqkv_h + b
//   -> q (scaled, [n,d]), k ([n,d]), vT ([d,n])
// ===========================================================================
__global__ __launch_bounds__(256, 2) void qkv_kernel(const float* __restrict__ bias)
{
    extern __shared__ __half sm[];
    __half* AsB = sm;
    __half* BsB = sm + 3*A_STG;

    const int tid = threadIdx.x;
    const int lane = tid & 31, w = tid >> 5;
    const int g = lane >> 2, t = lane & 3;
    const int m0 = blockIdx.x * 128, n0 = blockIdx.y * 128;
    const int wm = (w >> 2) * 64, wn = (w & 3) * 32;

    const int ar = tid >> 2, ak8 = (tid & 3) << 3;
    const int br = tid >> 4, bn8 = (tid & 15) << 3;
    const int mi = lane >> 3, rr = lane & 7;
    const int a_ro = ((mi & 1) << 3) + rr, a_co = (mi >> 1) << 3;

    float c[4][4][4];
    #pragma unroll
    for (int i = 0; i < 4; i++)
        #pragma unroll
        for (int j = 0; j < 4; j++)
            #pragma unroll
            for (int r = 0; r < 4; r++) c[i][j][r] = 0.f;

    auto loadStage = [&](int kb, int stg) {
        __half* A = AsB + stg*A_STG;
        __half* B = BsB + stg*B_STG;
        #pragma unroll
        for (int s = 0; s < 2; s++) {
            int row = ar + s*64;
            int gm = min(m0 + row, Mrows - 1);
            cpasync16(&A[row*40 + ak8], &g_xh[(size_t)gm*Cc + kb + ak8]);
        }
        #pragma unroll
        for (int s = 0; s < 2; s++) {
            int r = br + s*16;
            cpasync16(&B[r*136 + bn8], &g_wqh[(size_t)(kb + r)*N3 + n0 + bn8]);
        }
        CP_COMMIT();
    };

    loadStage(0, 0);
    loadStage(32, 1);
    int st = 0, ld = 2;
    for (int s = 0; s < 16; s++) {
        if (s < 15) { CP_WAIT(1); } else { CP_WAIT(0); }
        __syncthreads();
        if (s + 2 < 16) loadStage((s + 2)*32, ld);

        const __half* A = AsB + st*A_STG;
        const __half* B = BsB + st*B_STG;
        #pragma unroll
        for (int kc = 0; kc < 2; kc++) {
            unsigned a[4][4], b[2][4];
            #pragma unroll
            for (int mt = 0; mt < 4; mt++) {
                unsigned addr = (unsigned)__cvta_generic_to_shared(
                    &A[(wm + mt*16 + a_ro)*40 + kc*16 + a_co]);
                ldsm4(a[mt], addr);
            }
            #pragma unroll
            for (int ntp = 0; ntp < 2; ntp++) {
                unsigned addr = (unsigned)__cvta_generic_to_shared(
                    &B[(kc*16 + a_ro)*136 + wn + ntp*16 + a_co]);
                ldsm4t(b[ntp], addr);
            }
            #pragma unroll
            for (int mt = 0; mt < 4; mt++)
                #pragma unroll
                for (int nt = 0; nt < 4; nt++) {
                    unsigned b0 = (nt & 1) ? b[nt>>1][2] : b[nt>>1][0];
                    unsigned b1 = (nt & 1) ? b[nt>>1][3] : b[nt>>1][1];
                    mma16816(c[mt][nt], a[mt], b0, b1);
                }
        }
        st = (st == 2) ? 0 : st + 1;
        ld = (ld == 2) ? 0 : ld + 1;
    }

    const int sec = n0 >> 9;
    #pragma unroll
    for (int mt = 0; mt < 4; mt++) {
        #pragma unroll
        for (int nt = 0; nt < 4; nt++) {
            int n = n0 + wn + nt*8 + 2*t;
            float b0 = bias[n], b1 = bias[n + 1];
            int h = (n >> 5) & 15, d = n & 31;
            #pragma unroll
            for (int half_ = 0; half_ < 2; half_++) {
                int mrow = m0 + wm + mt*16 + g + half_*8;
                if (mrow >= Mrows) continue;
                float v0 = c[mt][nt][half_*2 + 0] + b0;
                float v1 = c[mt][nt][half_*2 + 1] + b1;
                int b_ = mrow / Nn, nr = mrow % Nn;
                size_t bh = (size_t)b_*Hh + h;
                if (sec == 0) {
                    __half2 hv = __floats2half2_rn(v0*SCALE, v1*SCALE);
                    *(__half2*)&g_q[(bh*Nn + nr)*HD + d] = hv;
                } else if (sec == 1) {
                    __half2 hv = __floats2half2_rn(v0, v1);
                    *(__half2*)&g_k[(bh*Nn + nr)*HD + d] = hv;
                } else {
                    g_vT[(bh*HD + d    )*VROW + nr] = __float2half(v0);
                    g_vT[(bh*HD + d + 1)*VROW + nr] = __float2half(v1);
                }
            }
        }
    }
}

// ===========================================================================
// Fused flash attention (R7 structure), fp16 bias table (half L2 traffic).
// ===========================================================================
__global__ __launch_bounds__(256) void attn_kernel()
{
    __shared__ __half Ks[2][64*40];   // [key][d] (pad 40)
    __shared__ __half Vs[2][32*72];   // [d][key] (pad 72)
    const int tid = threadIdx.x;
    const int lane = tid & 31, w = tid >> 5;
    const int g = lane >> 2, t = lane & 3;
    const int qbase = blockIdx.x * 128;
    const int bh = blockIdx.y;
    const int b = bh >> 4, h = bh & 15;

    const int qrA = qbase + w*16 + g;
    const int qrB = qrA + 8;
    const int qcA = min(qrA, Nn - 1), qcB = min(qrB, Nn - 1);

    const __half* bA = g_biash + ((size_t)h*Nn + qcA)*Nn;
    const __half* bB = g_biash + ((size_t)h*Nn + qcB)*Nn;

    // Q fragments (half2, scale folded by qkv)
    unsigned aq[2][4];
    {
        const __half* qp = g_q + (size_t)bh*Nn*HD;
        #pragma unroll
        for (int kc = 0; kc < 2; kc++) {
            aq[kc][0] = *(const unsigned*)&qp[(size_t)qcA*HD + kc*16 + 2*t];
            aq[kc][1] = *(const unsigned*)&qp[(size_t)qcB*HD + kc*16 + 2*t];
            aq[kc][2] = *(const unsigned*)&qp[(size_t)qcA*HD + kc*16 + 2*t + 8];
            aq[kc][3] = *(const unsigned*)&qp[(size_t)qcB*HD + kc*16 + 2*t + 8];
        }
    }

    const int kkey = tid >> 2, kd8 = (tid & 3) << 3;
    const int vd = tid >> 3, vk8 = (tid & 7) << 3;
    auto issue = [&](int tile) {
        int key0 = tile * 64, bf = tile & 1;
        cpasync16(&Ks[bf][kkey*40 + kd8], &g_k[((size_t)bh*Nn + key0 + kkey)*HD + kd8]);
        cpasync16(&Vs[bf][vd*72 + vk8],   &g_vT[((size_t)bh*HD + vd)*VROW + key0 + vk8]);
        CP_COMMIT();
    };

    float lA = 0.f, lB = 0.f;
    float o[4][4];
    #pragma unroll
    for (int i = 0; i < 4; i++)
        #pragma unroll
        for (int r = 0; r < 4; r++) o[i][r] = 0.f;

    issue(0);
    for (int tile = 0; tile < 12; tile++) {
        CP_WAIT(0);
        __syncthreads();
        if (tile + 1 < 12) issue(tile + 1);

        const __half* K = Ks[tile & 1];
        const __half* V = Vs[tile & 1];
        const int key0 = tile * 64;

        // ---- S = Q @ K^T ----
        float cS[8][4];
        #pragma unroll
        for (int nt = 0; nt < 8; nt++) {
            cS[nt][0] = cS[nt][1] = cS[nt][2] = cS[nt][3] = 0.f;
            #pragma unroll
            for (int kc = 0; kc < 2; kc++) {
                unsigned b0 = *(const unsigned*)&K[(nt*8 + g)*40 + kc*16 + 2*t];
                unsigned b1 = *(const unsigned*)&K[(nt*8 + g)*40 + kc*16 + 2*t + 8];
                mma16816(cS[nt], aq[kc], b0, b1);
            }
        }

        // ---- + bias (fp16 table), exp, sums, pack to half2 ----
        const bool lastTile = (key0 + 64 > Nn);
        float sumA = 0.f, sumB = 0.f;
        unsigned ph[8][2];
        #pragma unroll
        for (int nt = 0; nt < 8; nt++) {
            int j0 = key0 + nt*8 + 2*t;
            float2 vbA = __half22float2(*(const __half2*)&bA[j0]);
            float2 vbB = __half22float2(*(const __half2*)&bB[j0]);
            float p0 = __expf(cS[nt][0] + vbA.x);
            float p1 = __expf(cS[nt][1] + vbA.y);
            float p2 = __expf(cS[nt][2] + vbB.x);
            float p3 = __expf(cS[nt][3] + vbB.y);
            if (lastTile) {
                if (j0     >= Nn) { p0 = 0.f; p2 = 0.f; }
                if (j0 + 1 >= Nn) { p1 = 0.f; p3 = 0.f; }
            }
            sumA += p0 + p1; sumB += p2 + p3;
            ph[nt][0] = h2u(__floats2half2_rn(p0, p1));   // row g
            ph[nt][1] = h2u(__floats2half2_rn(p2, p3));   // row g+8
        }
        sumA += __shfl_xor_sync(0xffffffffu, sumA, 1);
        sumA += __shfl_xor_sync(0xffffffffu, sumA, 2);
        sumB += __shfl_xor_sync(0xffffffffu, sumB, 1);
        sumB += __shfl_xor_sync(0xffffffffu, sumB, 2);
        lA += sumA; lB += sumB;

        // ---- O += P @ V ----
        #pragma unroll
        for (int kc2 = 0; kc2 < 4; kc2++) {
            unsigned a[4] = { ph[2*kc2][0], ph[2*kc2][1],
                              ph[2*kc2+1][0], ph[2*kc2+1][1] };
            #pragma unroll
            for (int nt2 = 0; nt2 < 4; nt2++) {
                unsigned b0 = *(const unsigned*)&V[(nt2*8 + g)*72 + kc2*16 + 2*t];
                unsigned b1 = *(const unsigned*)&V[(nt2*8 + g)*72 + kc2*16 + 2*t + 8];
                mma16816(o[nt2], a, b0, b1);
            }
        }
    }

    float invA = 1.f / lA, invB = 1.f / lB;
    #pragma unroll
    for (int nt2 = 0; nt2 < 4; nt2++) {
        int d = h*HD + nt2*8 + 2*t;
        if (qrA < Nn) {
            __half2 hv = __floats2half2_rn(o[nt2][0]*invA, o[nt2][1]*invA);
            *(__half2*)&g_ao[((size_t)b*Nn + qrA)*Cc + d] = hv;
        }
        if (qrB < Nn) {
            __half2 hv = __floats2half2_rn(o[nt2][2]*invB, o[nt2][3]*invB);
            *(__half2*)&g_ao[((size_t)b*Nn + qrB)*Cc + d] = hv;
        }
    }
}

// ===========================================================================
// Projection (fp16 mma + ldmatrix + 3-stage cp.async): ao_h @ Wproj_h + b
// ===========================================================================
__global__ __launch_bounds__(256, 2) void proj_kernel(
    const float* __restrict__ bias, float* __restrict__ out)
{
    extern __shared__ __half sm[];
    __half* AsB = sm;
    __half* BsB = sm + 3*A_STG;

    const int tid = threadIdx.x;
    const int lane = tid & 31, w = tid >> 5;
    const int g = lane >> 2, t = lane & 3;
    const int m0 = blockIdx.x * 128, n0 = blockIdx.y * 128;
    const int wm = (w >> 2) * 64, wn = (w & 3) * 32;

    const int ar = tid >> 2, ak8 = (tid & 3) << 3;
    const int br = tid >> 4, bn8 = (tid & 15) << 3;
    const int mi = lane >> 3, rr = lane & 7;
    const int a_ro = ((mi & 1) << 3) + rr, a_co = (mi >> 1) << 3;

    float c[4][4][4];
    #pragma unroll
    for (int i = 0; i < 4; i++)
        #pragma unroll
        for (int j = 0; j < 4; j++)
            #pragma unroll
            for (int r = 0; r < 4; r++) c[i][j][r] = 0.f;

    auto loadStage = [&](int kb, int stg) {
        __half* A = AsB + stg*A_STG;
        __half* B = BsB + stg*B_STG;
        #pragma unroll
        for (int s = 0; s < 2; s++) {
            int row = ar + s*64;
            int gm = min(m0 + row, Mrows - 1);
            cpasync16(&A[row*40 + ak8], &g_ao[(size_t)gm*Cc + kb + ak8]);
        }
        #pragma unroll
        for (int s = 0; s < 2; s++) {
            int r = br + s*16;
            cpasync16(&B[r*136 + bn8], &g_wph[(size_t)(kb + r)*Cc + n0 + bn8]);
        }
        CP_COMMIT();
    };

    loadStage(0, 0);
    loadStage(32, 1);
    int st = 0, ld = 2;
    for (int s = 0; s < 16; s++) {
        if (s < 15) { CP_WAIT(1); } else { CP_WAIT(0); }
        __syncthreads();
        if (s + 2 < 16) loadStage((s + 2)*32, ld);

        const __half* A = AsB + st*A_STG;
        const __half* B = BsB + st*B_STG;
        #pragma unroll
        for (int kc = 0; kc < 2; kc++) {
            unsigned a[4][4], b[2][4];
            #pragma unroll
            for (int mt = 0; mt < 4; mt++) {
                unsigned addr = (unsigned)__cvta_generic_to_shared(
                    &A[(wm + mt*16 + a_ro)*40 + kc*16 + a_co]);
                ldsm4(a[mt], addr);
            }
            #pragma unroll
            for (int ntp = 0; ntp < 2; ntp++) {
                unsigned addr = (unsigned)__cvta_generic_to_shared(
                    &B[(kc*16 + a_ro)*136 + wn + ntp*16 + a_co]);
                ldsm4t(b[ntp], addr);
            }
            #pragma unroll
            for (int mt = 0; mt < 4; mt++)
                #pragma unroll
                for (int nt = 0; nt < 4; nt++) {
                    unsigned b0 = (nt & 1) ? b[nt>>1][2] : b[nt>>1][0];
                    unsigned b1 = (nt & 1) ? b[nt>>1][3] : b[nt>>1][1];
                    mma16816(c[mt][nt], a[mt], b0, b1);
                }
        }
        st = (st == 2) ? 0 : st + 1;
        ld = (ld == 2) ? 0 : ld + 1;
    }

    #pragma unroll
    for (int mt = 0; mt < 4; mt++) {
        #pragma unroll
        for (int nt = 0; nt < 4; nt++) {
            int n = n0 + wn + nt*8 + 2*t;
            float b0 = bias[n], b1 = bias[n + 1];
            #pragma unroll
            for (int half_ = 0; half_ < 2; half_++) {
                int mrow = m0 + wm + mt*16 + g + half_*8;
                if (mrow >= Mrows) continue;
                float v0 = c[mt][nt][half_*2 + 0] + b0;
                float v1 = c[mt][nt][half_*2 + 1] + b1;
                *(float2*)&out[(size_t)mrow*Cc + n] = make_float2(v0, v1);
            }
        }
    }
}

// ===========================================================================
extern "C" void kernel_launch(void* const* d_in, const int* in_sizes, int n_in,
                              void* d_out, int out_size)
{
    const float* x            = (const float*)d_in[0];
    const float* Wqkv         = (const float*)d_in[1];
    const float* bqkv         = (const float*)d_in[2];
    const float* Wproj        = (const float*)d_in[3];
    const float* bproj        = (const float*)d_in[4];
    const float* bt_target    = (const float*)d_in[5];
    const float* bt_temp      = (const float*)d_in[6];
    const float* tmp_tgt_tab  = (const float*)d_in[7];
    const float* tgt_tmp_tab  = (const float*)d_in[8];
    const float* tmp_tgt_line = (const float*)d_in[9];
    const float* tgt_tmp_line = (const float*)d_in[10];
    float* out = (float*)d_out;

    cudaFuncSetAttribute(qkv_kernel,  cudaFuncAttributeMaxDynamicSharedMemorySize, SMEM_GEMM);
    cudaFuncSetAttribute(proj_kernel, cudaFuncAttributeMaxDynamicSharedMemorySize, SMEM_GEMM);

    conv_kernel<<<1024, 256>>>(x, Wqkv, Wproj);
    bias_kernel<<<dim3(Nn, Hh), 256>>>(bt_target, bt_temp,
        tmp_tgt_tab, tgt_tmp_tab, tmp_tgt_line, tgt_tmp_line);
    qkv_kernel<<<dim3(93, 12), 256, SMEM_GEMM>>>(bqkv);
    attn_kernel<<<dim3(6, 256), 256>>>();
    proj_kernel<<<dim3(93, 4), 256, SMEM_GEMM>>>(bproj, out);
}

// round 10
// speedup vs baseline: 1.1866x; 1.1866x over previous
#include <cuda_runtime.h>
#include <cuda_fp16.h>

#define Bsz 16
#define Nn  740
#define Hh  16
#define HD  32
#define Cc  512
#define N3  1536
#define Mrows (Bsz*Nn)            // 11840
#define SCALE 0.1767766952966369f // 1/sqrt(32)
#define VROW 744                  // padded g_vT row (16B-aligned)

// ---------------- static device scratch (no allocations allowed) ----------
__device__ __align__(128) __half g_xh [(size_t)Mrows*Cc];
__device__ __align__(128) __half g_wqh[(size_t)Cc*N3];
__device__ __align__(128) __half g_wph[(size_t)Cc*Cc];
__device__ __align__(128) __half g_q  [(size_t)Bsz*Hh*Nn*HD + 64];
__device__ __align__(128) __half g_k  [(size_t)Bsz*Hh*Nn*HD + 32768]; // + tail pad
__device__ __align__(128) __half g_vT [(size_t)Bsz*Hh*HD*VROW + 1024];
__device__ __align__(128) __half g_ao [(size_t)Mrows*Cc];
__device__ float g_bias[(size_t)Hh*Nn*Nn + 64];

// ---------------- helpers --------------------------------------------------
__device__ __forceinline__ void mma16816(float* c, const unsigned* a,
                                         unsigned b0, unsigned b1) {
    asm volatile(
        "mma.sync.aligned.m16n8k16.row.col.f32.f16.f16.f32 "
        "{%0,%1,%2,%3}, {%4,%5,%6,%7}, {%8,%9}, {%0,%1,%2,%3};\n"
        : "+f"(c[0]), "+f"(c[1]), "+f"(c[2]), "+f"(c[3])
        : "r"(a[0]), "r"(a[1]), "r"(a[2]), "r"(a[3]), "r"(b0), "r"(b1));
}
__device__ __forceinline__ void ldsm4(unsigned* r, unsigned addr) {
    asm volatile("ldmatrix.sync.aligned.m8n8.x4.shared.b16 {%0,%1,%2,%3}, [%4];\n"
                 : "=r"(r[0]), "=r"(r[1]), "=r"(r[2]), "=r"(r[3]) : "r"(addr));
}
__device__ __forceinline__ void ldsm4t(unsigned* r, unsigned addr) {
    asm volatile("ldmatrix.sync.aligned.m8n8.x4.trans.shared.b16 {%0,%1,%2,%3}, [%4];\n"
                 : "=r"(r[0]), "=r"(r[1]), "=r"(r[2]), "=r"(r[3]) : "r"(addr));
}
__device__ __forceinline__ void cpasync16(void* sdst, const void* gsrc) {
    unsigned sa = (unsigned)__cvta_generic_to_shared(sdst);
    asm volatile("cp.async.cg.shared.global [%0], [%1], 16;\n" :: "r"(sa), "l"(gsrc));
}
#define CP_COMMIT() asm volatile("cp.async.commit_group;\n")
#define CP_WAIT(N)  asm volatile("cp.async.wait_group %0;\n" :: "n"(N))
__device__ __forceinline__ unsigned h2u(__half2 h) { return *(unsigned*)&h; }

// GEMM stage sizes in halves: A [128][40], B [32][136]
#define A_STG (128*40)
#define B_STG (32*136)
#define SMEM_GEMM (3*(A_STG + B_STG)*2)

// ===========================================================================
// fp32 -> fp16 conversion of x, W_qkv, W_proj
// ===========================================================================
__global__ __launch_bounds__(256) void conv_kernel(
    const float* __restrict__ x, const float* __restrict__ wq,
    const float* __restrict__ wp)
{
    const int XN = Mrows*Cc/4, QN = Cc*N3/4, PN = Cc*Cc/4;
    const int total = XN + QN + PN;
    const int stride = gridDim.x * blockDim.x;
    for (int i = blockIdx.x*blockDim.x + threadIdx.x; i < total; i += stride) {
        const float4* src; __half* dst; int j = i;
        if (j < XN)           { src = (const float4*)x;  dst = g_xh; }
        else if (j < XN + QN) { j -= XN; src = (const float4*)wq; dst = g_wqh; }
        else                  { j -= XN + QN; src = (const float4*)wp; dst = g_wph; }
        float4 f = src[j];
        __half2 h0 = __floats2half2_rn(f.x, f.y);
        __half2 h1 = __floats2half2_rn(f.z, f.w);
        *(uint2*)&dst[(size_t)j*4] = make_uint2(h2u(h0), h2u(h1));
    }
}

// ===========================================================================
// Bias precompute: g_bias[h][i][j] (fp32, L2-resident)
// ===========================================================================
__global__ __launch_bounds__(256) void bias_kernel(
    const float* __restrict__ bt_target, const float* __restrict__ bt_temp,
    const float* __restrict__ tmp_tgt_tab, const float* __restrict__ tgt_tmp_tab,
    const float* __restrict__ tmp_tgt_line, const float* __restrict__ tgt_tmp_line)
{
    const int i = blockIdx.x, h = blockIdx.y;
    const bool tmpR = i < 256;
    int r0, r1; float rowline;
    if (tmpR) { r0 = i >> 4; r1 = i & 15; rowline = tgt_tmp_tab[h*256 + i]; }
    else      { int a = i - 256; r0 = a/22; r1 = a%22; rowline = tmp_tgt_tab[h*484 + a]; }
    float* dst = g_bias + ((size_t)h*Nn + i)*Nn;
    for (int j = threadIdx.x; j < Nn; j += 256) {
        float bv;
        if (j < 256) {
            if (tmpR) {
                int idx = (r0 - (j >> 4) + 15)*31 + (r1 - (j & 15) + 15);
                bv = bt_temp[idx*Hh + h];
            } else bv = rowline + tmp_tgt_line[h*256 + j];
        } else {
            int cc = j - 256;
            if (tmpR) bv = rowline + tgt_tmp_line[h*484 + cc];
            else {
                int idx = (r0 - cc/22 + 21)*43 + (r1 - cc%22 + 21);
                bv = bt_target[idx*Hh + h];
            }
        }
        dst[j] = bv;
    }
}

// ===========================================================================
// QKV GEMM (fp16 mma + ldmatrix + 3-stage cp.async): x_h @ Wqkv_h + b
//   -> q (scaled, [n,d]), k ([n,d]), vT ([d,n])
// ===========================================================================
__global__ __launch_bounds__(256, 2) void qkv_kernel(const float* __restrict__ bias)
{
    extern __shared__ __half sm[];
    __half* AsB = sm;
    __half* BsB = sm + 3*A_STG;

    const int tid = threadIdx.x;
    const int lane = tid & 31, w = tid >> 5;
    const int g = lane >> 2, t = lane & 3;
    const int m0 = blockIdx.x * 128, n0 = blockIdx.y * 128;
    const int wm = (w >> 2) * 64, wn = (w & 3) * 32;

    const int ar = tid >> 2, ak8 = (tid & 3) << 3;
    const int br = tid >> 4, bn8 = (tid & 15) << 3;
    const int mi = lane >> 3, rr = lane & 7;
    const int a_ro = ((mi & 1) << 3) + rr, a_co = (mi >> 1) << 3;

    float c[4][4][4];
    #pragma unroll
    for (int i = 0; i < 4; i++)
        #pragma unroll
        for (int j = 0; j < 4; j++)
            #pragma unroll
            for (int r = 0; r < 4; r++) c[i][j][r] = 0.f;

    auto loadStage = [&](int kb, int stg) {
        __half* A = AsB + stg*A_STG;
        __half* B = BsB + stg*B_STG;
        #pragma unroll
        for (int s = 0; s < 2; s++) {
            int row = ar + s*64;
            int gm = min(m0 + row, Mrows - 1);
            cpasync16(&A[row*40 + ak8], &g_xh[(size_t)gm*Cc + kb + ak8]);
        }
        #pragma unroll
        for (int s = 0; s < 2; s++) {
            int r = br + s*16;
            cpasync16(&B[r*136 + bn8], &g_wqh[(size_t)(kb + r)*N3 + n0 + bn8]);
        }
        CP_COMMIT();
    };

    loadStage(0, 0);
    loadStage(32, 1);
    int st = 0, ld = 2;
    for (int s = 0; s < 16; s++) {
        if (s < 15) { CP_WAIT(1); } else { CP_WAIT(0); }
        __syncthreads();
        if (s + 2 < 16) loadStage((s + 2)*32, ld);

        const __half* A = AsB + st*A_STG;
        const __half* B = BsB + st*B_STG;
        #pragma unroll
        for (int kc = 0; kc < 2; kc++) {
            unsigned a[4][4], b[2][4];
            #pragma unroll
            for (int mt = 0; mt < 4; mt++) {
                unsigned addr = (unsigned)__cvta_generic_to_shared(
                    &A[(wm + mt*16 + a_ro)*40 + kc*16 + a_co]);
                ldsm4(a[mt], addr);
            }
            #pragma unroll
            for (int ntp = 0; ntp < 2; ntp++) {
                unsigned addr = (unsigned)__cvta_generic_to_shared(
                    &B[(kc*16 + a_ro)*136 + wn + ntp*16 + a_co]);
                ldsm4t(b[ntp], addr);
            }
            #pragma unroll
            for (int mt = 0; mt < 4; mt++)
                #pragma unroll
                for (int nt = 0; nt < 4; nt++) {
                    unsigned b0 = (nt & 1) ? b[nt>>1][2] : b[nt>>1][0];
                    unsigned b1 = (nt & 1) ? b[nt>>1][3] : b[nt>>1][1];
                    mma16816(c[mt][nt], a[mt], b0, b1);
                }
        }
        st = (st == 2) ? 0 : st + 1;
        ld = (ld == 2) ? 0 : ld + 1;
    }

    const int sec = n0 >> 9;
    #pragma unroll
    for (int mt = 0; mt < 4; mt++) {
        #pragma unroll
        for (int nt = 0; nt < 4; nt++) {
            int n = n0 + wn + nt*8 + 2*t;
            float b0 = bias[n], b1 = bias[n + 1];
            int h = (n >> 5) & 15, d = n & 31;
            #pragma unroll
            for (int half_ = 0; half_ < 2; half_++) {
                int mrow = m0 + wm + mt*16 + g + half_*8;
                if (mrow >= Mrows) continue;
                float v0 = c[mt][nt][half_*2 + 0] + b0;
                float v1 = c[mt][nt][half_*2 + 1] + b1;
                int b_ = mrow / Nn, nr = mrow % Nn;
                size_t bh = (size_t)b_*Hh + h;
                if (sec == 0) {
                    __half2 hv = __floats2half2_rn(v0*SCALE, v1*SCALE);
                    *(__half2*)&g_q[(bh*Nn + nr)*HD + d] = hv;
                } else if (sec == 1) {
                    __half2 hv = __floats2half2_rn(v0, v1);
                    *(__half2*)&g_k[(bh*Nn + nr)*HD + d] = hv;
                } else {
                    g_vT[(bh*HD + d    )*VROW + nr] = __float2half(v0);
                    g_vT[(bh*HD + d + 1)*VROW + nr] = __float2half(v1);
                }
            }
        }
    }
}

// ===========================================================================
// Fused flash attention (R7 details), fused S-pair -> exp -> PV pipeline:
// shorter dep chains, ~24 fewer live registers.
// ===========================================================================
__global__ __launch_bounds__(256) void attn_kernel()
{
    __shared__ __half Ks[2][64*40];   // [key][d] (pad 40)
    __shared__ __half Vs[2][32*72];   // [d][key] (pad 72)
    const int tid = threadIdx.x;
    const int lane = tid & 31, w = tid >> 5;
    const int g = lane >> 2, t = lane & 3;
    const int qbase = blockIdx.x * 128;
    const int bh = blockIdx.y;
    const int b = bh >> 4, h = bh & 15;

    const int qrA = qbase + w*16 + g;
    const int qrB = qrA + 8;
    const int qcA = min(qrA, Nn - 1), qcB = min(qrB, Nn - 1);

    const float* bA = g_bias + ((size_t)h*Nn + qcA)*Nn;
    const float* bB = g_bias + ((size_t)h*Nn + qcB)*Nn;

    // Q fragments (half2, scale folded by qkv)
    unsigned aq[2][4];
    {
        const __half* qp = g_q + (size_t)bh*Nn*HD;
        #pragma unroll
        for (int kc = 0; kc < 2; kc++) {
            aq[kc][0] = *(const unsigned*)&qp[(size_t)qcA*HD + kc*16 + 2*t];
            aq[kc][1] = *(const unsigned*)&qp[(size_t)qcB*HD + kc*16 + 2*t];
            aq[kc][2] = *(const unsigned*)&qp[(size_t)qcA*HD + kc*16 + 2*t + 8];
            aq[kc][3] = *(const unsigned*)&qp[(size_t)qcB*HD + kc*16 + 2*t + 8];
        }
    }

    const int kkey = tid >> 2, kd8 = (tid & 3) << 3;
    const int vd = tid >> 3, vk8 = (tid & 7) << 3;
    auto issue = [&](int tile) {
        int key0 = tile * 64, bf = tile & 1;
        cpasync16(&Ks[bf][kkey*40 + kd8], &g_k[((size_t)bh*Nn + key0 + kkey)*HD + kd8]);
        cpasync16(&Vs[bf][vd*72 + vk8],   &g_vT[((size_t)bh*HD + vd)*VROW + key0 + vk8]);
        CP_COMMIT();
    };

    float lA = 0.f, lB = 0.f;
    float o[4][4];
    #pragma unroll
    for (int i = 0; i < 4; i++)
        #pragma unroll
        for (int r = 0; r < 4; r++) o[i][r] = 0.f;

    issue(0);
    for (int tile = 0; tile < 12; tile++) {
        CP_WAIT(0);
        __syncthreads();
        if (tile + 1 < 12) issue(tile + 1);

        const __half* K = Ks[tile & 1];
        const __half* V = Vs[tile & 1];
        const int key0 = tile * 64;
        const bool lastTile = (key0 + 64 > Nn);
        float sumA = 0.f, sumB = 0.f;

        // 4 independent pair-units: S (2 n-frags) -> exp -> PV k-chunk np
        #pragma unroll
        for (int np = 0; np < 4; np++) {
            const int nt0 = 2*np, nt1 = 2*np + 1;
            float c0[4] = {0.f, 0.f, 0.f, 0.f};
            float c1[4] = {0.f, 0.f, 0.f, 0.f};
            #pragma unroll
            for (int kc = 0; kc < 2; kc++) {
                unsigned kb0 = *(const unsigned*)&K[(nt0*8 + g)*40 + kc*16 + 2*t];
                unsigned kb1 = *(const unsigned*)&K[(nt0*8 + g)*40 + kc*16 + 2*t + 8];
                mma16816(c0, aq[kc], kb0, kb1);
                unsigned kb2 = *(const unsigned*)&K[(nt1*8 + g)*40 + kc*16 + 2*t];
                unsigned kb3 = *(const unsigned*)&K[(nt1*8 + g)*40 + kc*16 + 2*t + 8];
                mma16816(c1, aq[kc], kb2, kb3);
            }
            int j0 = key0 + nt0*8 + 2*t;
            int j1 = key0 + nt1*8 + 2*t;
            float2 vbA0 = *(const float2*)&bA[j0];
            float2 vbB0 = *(const float2*)&bB[j0];
            float2 vbA1 = *(const float2*)&bA[j1];
            float2 vbB1 = *(const float2*)&bB[j1];
            float p00 = __expf(c0[0] + vbA0.x);
            float p01 = __expf(c0[1] + vbA0.y);
            float p02 = __expf(c0[2] + vbB0.x);
            float p03 = __expf(c0[3] + vbB0.y);
            float p10 = __expf(c1[0] + vbA1.x);
            float p11 = __expf(c1[1] + vbA1.y);
            float p12 = __expf(c1[2] + vbB1.x);
            float p13 = __expf(c1[3] + vbB1.y);
            if (lastTile) {
                if (j0     >= Nn) { p00 = 0.f; p02 = 0.f; }
                if (j0 + 1 >= Nn) { p01 = 0.f; p03 = 0.f; }
                if (j1     >= Nn) { p10 = 0.f; p12 = 0.f; }
                if (j1 + 1 >= Nn) { p11 = 0.f; p13 = 0.f; }
            }
            sumA += p00 + p01 + p10 + p11;
            sumB += p02 + p03 + p12 + p13;
            // A-fragment for PV k-chunk np (rows g / g+8, k = pair keys)
            unsigned a[4] = { h2u(__floats2half2_rn(p00, p01)),
                              h2u(__floats2half2_rn(p02, p03)),
                              h2u(__floats2half2_rn(p10, p11)),
                              h2u(__floats2half2_rn(p12, p13)) };
            #pragma unroll
            for (int nt2 = 0; nt2 < 4; nt2++) {
                unsigned b0 = *(const unsigned*)&V[(nt2*8 + g)*72 + np*16 + 2*t];
                unsigned b1 = *(const unsigned*)&V[(nt2*8 + g)*72 + np*16 + 2*t + 8];
                mma16816(o[nt2], a, b0, b1);
            }
        }

        sumA += __shfl_xor_sync(0xffffffffu, sumA, 1);
        sumA += __shfl_xor_sync(0xffffffffu, sumA, 2);
        sumB += __shfl_xor_sync(0xffffffffu, sumB, 1);
        sumB += __shfl_xor_sync(0xffffffffu, sumB, 2);
        lA += sumA; lB += sumB;
    }

    float invA = 1.f / lA, invB = 1.f / lB;
    #pragma unroll
    for (int nt2 = 0; nt2 < 4; nt2++) {
        int d = h*HD + nt2*8 + 2*t;
        if (qrA < Nn) {
            __half2 hv = __floats2half2_rn(o[nt2][0]*invA, o[nt2][1]*invA);
            *(__half2*)&g_ao[((size_t)b*Nn + qrA)*Cc + d] = hv;
        }
        if (qrB < Nn) {
            __half2 hv = __floats2half2_rn(o[nt2][2]*invB, o[nt2][3]*invB);
            *(__half2*)&g_ao[((size_t)b*Nn + qrB)*Cc + d] = hv;
        }
    }
}

// ===========================================================================
// Projection (fp16 mma + ldmatrix + 3-stage cp.async): ao_h @ Wproj_h + b
// ===========================================================================
__global__ __launch_bounds__(256, 2) void proj_kernel(
    const float* __restrict__ bias, float* __restrict__ out)
{
    extern __shared__ __half sm[];
    __half* AsB = sm;
    __half* BsB = sm + 3*A_STG;

    const int tid = threadIdx.x;
    const int lane = tid & 31, w = tid >> 5;
    const int g = lane >> 2, t = lane & 3;
    const int m0 = blockIdx.x * 128, n0 = blockIdx.y * 128;
    const int wm = (w >> 2) * 64, wn = (w & 3) * 32;

    const int ar = tid >> 2, ak8 = (tid & 3) << 3;
    const int br = tid >> 4, bn8 = (tid & 15) << 3;
    const int mi = lane >> 3, rr = lane & 7;
    const int a_ro = ((mi & 1) << 3) + rr, a_co = (mi >> 1) << 3;

    float c[4][4][4];
    #pragma unroll
    for (int i = 0; i < 4; i++)
        #pragma unroll
        for (int j = 0; j < 4; j++)
            #pragma unroll
            for (int r = 0; r < 4; r++) c[i][j][r] = 0.f;

    auto loadStage = [&](int kb, int stg) {
        __half* A = AsB + stg*A_STG;
        __half* B = BsB + stg*B_STG;
        #pragma unroll
        for (int s = 0; s < 2; s++) {
            int row = ar + s*64;
            int gm = min(m0 + row, Mrows - 1);
            cpasync16(&A[row*40 + ak8], &g_ao[(size_t)gm*Cc + kb + ak8]);
        }
        #pragma unroll
        for (int s = 0; s < 2; s++) {
            int r = br + s*16;
            cpasync16(&B[r*136 + bn8], &g_wph[(size_t)(kb + r)*Cc + n0 + bn8]);
        }
        CP_COMMIT();
    };

    loadStage(0, 0);
    loadStage(32, 1);
    int st = 0, ld = 2;
    for (int s = 0; s < 16; s++) {
        if (s < 15) { CP_WAIT(1); } else { CP_WAIT(0); }
        __syncthreads();
        if (s + 2 < 16) loadStage((s + 2)*32, ld);

        const __half* A = AsB + st*A_STG;
        const __half* B = BsB + st*B_STG;
        #pragma unroll
        for (int kc = 0; kc < 2; kc++) {
            unsigned a[4][4], b[2][4];
            #pragma unroll
            for (int mt = 0; mt < 4; mt++) {
                unsigned addr = (unsigned)__cvta_generic_to_shared(
                    &A[(wm + mt*16 + a_ro)*40 + kc*16 + a_co]);
                ldsm4(a[mt], addr);
            }
            #pragma unroll
            for (int ntp = 0; ntp < 2; ntp++) {
                unsigned addr = (unsigned)__cvta_generic_to_shared(
                    &B[(kc*16 + a_ro)*136 + wn + ntp*16 + a_co]);
                ldsm4t(b[ntp], addr);
            }
            #pragma unroll
            for (int mt = 0; mt < 4; mt++)
                #pragma unroll
                for (int nt = 0; nt < 4; nt++) {
                    unsigned b0 = (nt & 1) ? b[nt>>1][2] : b[nt>>1][0];
                    unsigned b1 = (nt & 1) ? b[nt>>1][3] : b[nt>>1][1];
                    mma16816(c[mt][nt], a[mt], b0, b1);
                }
        }
        st = (st == 2) ? 0 : st + 1;
        ld = (ld == 2) ? 0 : ld + 1;
    }

    #pragma unroll
    for (int mt = 0; mt < 4; mt++) {
        #pragma unroll
        for (int nt = 0; nt < 4; nt++) {
            int n = n0 + wn + nt*8 + 2*t;
            float b0 = bias[n], b1 = bias[n + 1];
            #pragma unroll
            for (int half_ = 0; half_ < 2; half_++) {
                int mrow = m0 + wm + mt*16 + g + half_*8;
                if (mrow >= Mrows) continue;
                float v0 = c[mt][nt][half_*2 + 0] + b0;
                float v1 = c[mt][nt][half_*2 + 1] + b1;
                *(float2*)&out[(size_t)mrow*Cc + n] = make_float2(v0, v1);
            }
        }
    }
}

// ===========================================================================
extern "C" void kernel_launch(void* const* d_in, const int* in_sizes, int n_in,
                              void* d_out, int out_size)
{
    const float* x            = (const float*)d_in[0];
    const float* Wqkv         = (const float*)d_in[1];
    const float* bqkv         = (const float*)d_in[2];
    const float* Wproj        = (const float*)d_in[3];
    const float* bproj        = (const float*)d_in[4];
    const float* bt_target    = (const float*)d_in[5];
    const float* bt_temp      = (const float*)d_in[6];
    const float* tmp_tgt_tab  = (const float*)d_in[7];
    const float* tgt_tmp_tab  = (const float*)d_in[8];
    const float* tmp_tgt_line = (const float*)d_in[9];
    const float* tgt_tmp_line = (const float*)d_in[10];
    float* out = (float*)d_out;

    cudaFuncSetAttribute(qkv_kernel,  cudaFuncAttributeMaxDynamicSharedMemorySize, SMEM_GEMM);
    cudaFuncSetAttribute(proj_kernel, cudaFuncAttributeMaxDynamicSharedMemorySize, SMEM_GEMM);

    conv_kernel<<<1024, 256>>>(x, Wqkv, Wproj);
    bias_kernel<<<dim3(Nn, Hh), 256>>>(bt_target, bt_temp,
        tmp_tgt_tab, tgt_tmp_tab, tmp_tgt_line, tgt_tmp_line);
    qkv_kernel<<<dim3(93, 12), 256, SMEM_GEMM>>>(bqkv);
    attn_kernel<<<dim3(6, 256), 256>>>();
    proj_kernel<<<dim3(93, 4), 256, SMEM_GEMM>>>(bproj, out);
}

// round 11
// speedup vs baseline: 1.2237x; 1.0313x over previous
#include <cuda_runtime.h>
#include <cuda_fp16.h>

#define Bsz 16
#define Nn  740
#define Hh  16
#define HD  32
#define Cc  512
#define N3  1536
#define Mrows (Bsz*Nn)            // 11840
#define SCALE 0.1767766952966369f // 1/sqrt(32)
#define LOG2E 1.4426950408889634f
#define QSCALE (SCALE*LOG2E)      // exp(x) == ex2(x*log2e)
#define VROW 744                  // padded g_vT row (16B-aligned)

// ---------------- static device scratch (no allocations allowed) ----------
__device__ __align__(128) __half g_xh [(size_t)Mrows*Cc];
__device__ __align__(128) __half g_wqh[(size_t)Cc*N3];
__device__ __align__(128) __half g_wph[(size_t)Cc*Cc];
__device__ __align__(128) __half g_q  [(size_t)Bsz*Hh*Nn*HD + 64];
__device__ __align__(128) __half g_k  [(size_t)Bsz*Hh*Nn*HD + 32768]; // + tail pad
__device__ __align__(128) __half g_vT [(size_t)Bsz*Hh*HD*VROW + 1024];
__device__ __align__(128) __half g_ao [(size_t)Mrows*Cc];
__device__ float g_bias[(size_t)Hh*Nn*Nn + 64];   // pre-multiplied by LOG2E

// ---------------- helpers --------------------------------------------------
__device__ __forceinline__ void mma16816(float* c, const unsigned* a,
                                         unsigned b0, unsigned b1) {
    asm volatile(
        "mma.sync.aligned.m16n8k16.row.col.f32.f16.f16.f32 "
        "{%0,%1,%2,%3}, {%4,%5,%6,%7}, {%8,%9}, {%0,%1,%2,%3};\n"
        : "+f"(c[0]), "+f"(c[1]), "+f"(c[2]), "+f"(c[3])
        : "r"(a[0]), "r"(a[1]), "r"(a[2]), "r"(a[3]), "r"(b0), "r"(b1));
}
__device__ __forceinline__ void ldsm4(unsigned* r, unsigned addr) {
    asm volatile("ldmatrix.sync.aligned.m8n8.x4.shared.b16 {%0,%1,%2,%3}, [%4];\n"
                 : "=r"(r[0]), "=r"(r[1]), "=r"(r[2]), "=r"(r[3]) : "r"(addr));
}
__device__ __forceinline__ void ldsm4t(unsigned* r, unsigned addr) {
    asm volatile("ldmatrix.sync.aligned.m8n8.x4.trans.shared.b16 {%0,%1,%2,%3}, [%4];\n"
                 : "=r"(r[0]), "=r"(r[1]), "=r"(r[2]), "=r"(r[3]) : "r"(addr));
}
__device__ __forceinline__ void cpasync16(void* sdst, const void* gsrc) {
    unsigned sa = (unsigned)__cvta_generic_to_shared(sdst);
    asm volatile("cp.async.cg.shared.global [%0], [%1], 16;\n" :: "r"(sa), "l"(gsrc));
}
#define CP_COMMIT() asm volatile("cp.async.commit_group;\n")
#define CP_WAIT(N)  asm volatile("cp.async.wait_group %0;\n" :: "n"(N))
__device__ __forceinline__ unsigned h2u(__half2 h) { return *(unsigned*)&h; }
__device__ __forceinline__ float ex2f(float x) {
    float y; asm("ex2.approx.ftz.f32 %0, %1;" : "=f"(y) : "f"(x)); return y;
}

// GEMM stage sizes in halves: A [128][40], B [32][136]
#define A_STG (128*40)
#define B_STG (32*136)
#define SMEM_GEMM (3*(A_STG + B_STG)*2)

// ===========================================================================
// prep: grid.y < 16 -> bias rows (h = blockIdx.y); grid.y == 16 -> fp32->fp16
// conversion of x / W_qkv / W_proj (grid-stride over blockIdx.x).
// ===========================================================================
__global__ __launch_bounds__(256) void prep_kernel(
    const float* __restrict__ x, const float* __restrict__ wq,
    const float* __restrict__ wp,
    const float* __restrict__ bt_target, const float* __restrict__ bt_temp,
    const float* __restrict__ tmp_tgt_tab, const float* __restrict__ tgt_tmp_tab,
    const float* __restrict__ tmp_tgt_line, const float* __restrict__ tgt_tmp_line)
{
    if (blockIdx.y == 16) {
        const int XN = Mrows*Cc/4, QN = Cc*N3/4, PN = Cc*Cc/4;
        const int total = XN + QN + PN;
        const int stride = gridDim.x * blockDim.x;
        for (int i = blockIdx.x*blockDim.x + threadIdx.x; i < total; i += stride) {
            const float4* src; __half* dst; int j = i;
            if (j < XN)           { src = (const float4*)x;  dst = g_xh; }
            else if (j < XN + QN) { j -= XN; src = (const float4*)wq; dst = g_wqh; }
            else                  { j -= XN + QN; src = (const float4*)wp; dst = g_wph; }
            float4 f = src[j];
            __half2 h0 = __floats2half2_rn(f.x, f.y);
            __half2 h1 = __floats2half2_rn(f.z, f.w);
            *(uint2*)&dst[(size_t)j*4] = make_uint2(h2u(h0), h2u(h1));
        }
        return;
    }
    const int i = blockIdx.x, h = blockIdx.y;
    const bool tmpR = i < 256;
    int r0, r1; float rowline;
    if (tmpR) { r0 = i >> 4; r1 = i & 15; rowline = tgt_tmp_tab[h*256 + i]; }
    else      { int a = i - 256; r0 = a/22; r1 = a%22; rowline = tmp_tgt_tab[h*484 + a]; }
    float* dst = g_bias + ((size_t)h*Nn + i)*Nn;
    for (int j = threadIdx.x; j < Nn; j += 256) {
        float bv;
        if (j < 256) {
            if (tmpR) {
                int idx = (r0 - (j >> 4) + 15)*31 + (r1 - (j & 15) + 15);
                bv = bt_temp[idx*Hh + h];
            } else bv = rowline + tmp_tgt_line[h*256 + j];
        } else {
            int cc = j - 256;
            if (tmpR) bv = rowline + tgt_tmp_line[h*484 + cc];
            else {
                int idx = (r0 - cc/22 + 21)*43 + (r1 - cc%22 + 21);
                bv = bt_target[idx*Hh + h];
            }
        }
        dst[j] = bv * LOG2E;
    }
}

// ===========================================================================
// QKV GEMM (fp16 mma + ldmatrix + 3-stage cp.async): x_h @ Wqkv_h + b
//   -> q (scaled*log2e, [n,d]), k ([n,d]), vT ([d,n])
// ===========================================================================
__global__ __launch_bounds__(256, 2) void qkv_kernel(const float* __restrict__ bias)
{
    extern __shared__ __half sm[];
    __half* AsB = sm;
    __half* BsB = sm + 3*A_STG;

    const int tid = threadIdx.x;
    const int lane = tid & 31, w = tid >> 5;
    const int g = lane >> 2, t = lane & 3;
    const int m0 = blockIdx.x * 128, n0 = blockIdx.y * 128;
    const int wm = (w >> 2) * 64, wn = (w & 3) * 32;

    const int ar = tid >> 2, ak8 = (tid & 3) << 3;
    const int br = tid >> 4, bn8 = (tid & 15) << 3;
    const int mi = lane >> 3, rr = lane & 7;
    const int a_ro = ((mi & 1) << 3) + rr, a_co = (mi >> 1) << 3;

    float c[4][4][4];
    #pragma unroll
    for (int i = 0; i < 4; i++)
        #pragma unroll
        for (int j = 0; j < 4; j++)
            #pragma unroll
            for (int r = 0; r < 4; r++) c[i][j][r] = 0.f;

    auto loadStage = [&](int kb, int stg) {
        __half* A = AsB + stg*A_STG;
        __half* B = BsB + stg*B_STG;
        #pragma unroll
        for (int s = 0; s < 2; s++) {
            int row = ar + s*64;
            int gm = min(m0 + row, Mrows - 1);
            cpasync16(&A[row*40 + ak8], &g_xh[(size_t)gm*Cc + kb + ak8]);
        }
        #pragma unroll
        for (int s = 0; s < 2; s++) {
            int r = br + s*16;
            cpasync16(&B[r*136 + bn8], &g_wqh[(size_t)(kb + r)*N3 + n0 + bn8]);
        }
        CP_COMMIT();
    };

    loadStage(0, 0);
    loadStage(32, 1);
    int st = 0, ld = 2;
    for (int s = 0; s < 16; s++) {
        if (s < 15) { CP_WAIT(1); } else { CP_WAIT(0); }
        __syncthreads();
        if (s + 2 < 16) loadStage((s + 2)*32, ld);

        const __half* A = AsB + st*A_STG;
        const __half* B = BsB + st*B_STG;
        #pragma unroll
        for (int kc = 0; kc < 2; kc++) {
            unsigned a[4][4], b[2][4];
            #pragma unroll
            for (int mt = 0; mt < 4; mt++) {
                unsigned addr = (unsigned)__cvta_generic_to_shared(
                    &A[(wm + mt*16 + a_ro)*40 + kc*16 + a_co]);
                ldsm4(a[mt], addr);
            }
            #pragma unroll
            for (int ntp = 0; ntp < 2; ntp++) {
                unsigned addr = (unsigned)__cvta_generic_to_shared(
                    &B[(kc*16 + a_ro)*136 + wn + ntp*16 + a_co]);
                ldsm4t(b[ntp], addr);
            }
            #pragma unroll
            for (int mt = 0; mt < 4; mt++)
                #pragma unroll
                for (int nt = 0; nt < 4; nt++) {
                    unsigned b0 = (nt & 1) ? b[nt>>1][2] : b[nt>>1][0];
                    unsigned b1 = (nt & 1) ? b[nt>>1][3] : b[nt>>1][1];
                    mma16816(c[mt][nt], a[mt], b0, b1);
                }
        }
        st = (st == 2) ? 0 : st + 1;
        ld = (ld == 2) ? 0 : ld + 1;
    }

    const int sec = n0 >> 9;
    #pragma unroll
    for (int mt = 0; mt < 4; mt++) {
        #pragma unroll
        for (int nt = 0; nt < 4; nt++) {
            int n = n0 + wn + nt*8 + 2*t;
            float b0 = bias[n], b1 = bias[n + 1];
            int h = (n >> 5) & 15, d = n & 31;
            #pragma unroll
            for (int half_ = 0; half_ < 2; half_++) {
                int mrow = m0 + wm + mt*16 + g + half_*8;
                if (mrow >= Mrows) continue;
                float v0 = c[mt][nt][half_*2 + 0] + b0;
                float v1 = c[mt][nt][half_*2 + 1] + b1;
                int b_ = mrow / Nn, nr = mrow % Nn;
                size_t bh = (size_t)b_*Hh + h;
                if (sec == 0) {
                    __half2 hv = __floats2half2_rn(v0*QSCALE, v1*QSCALE);
                    *(__half2*)&g_q[(bh*Nn + nr)*HD + d] = hv;
                } else if (sec == 1) {
                    __half2 hv = __floats2half2_rn(v0, v1);
                    *(__half2*)&g_k[(bh*Nn + nr)*HD + d] = hv;
                } else {
                    g_vT[(bh*HD + d    )*VROW + nr] = __float2half(v0);
                    g_vT[(bh*HD + d + 1)*VROW + nr] = __float2half(v1);
                }
            }
        }
    }
}

// ===========================================================================
// Fused flash attention (R10 structure) + ex2 softmax + deferred l-reduction.
// ===========================================================================
__global__ __launch_bounds__(256) void attn_kernel()
{
    __shared__ __half Ks[2][64*40];   // [key][d] (pad 40)
    __shared__ __half Vs[2][32*72];   // [d][key] (pad 72)
    const int tid = threadIdx.x;
    const int lane = tid & 31, w = tid >> 5;
    const int g = lane >> 2, t = lane & 3;
    const int qbase = blockIdx.x * 128;
    const int bh = blockIdx.y;
    const int b = bh >> 4, h = bh & 15;

    const int qrA = qbase + w*16 + g;
    const int qrB = qrA + 8;
    const int qcA = min(qrA, Nn - 1), qcB = min(qrB, Nn - 1);

    const float* bA = g_bias + ((size_t)h*Nn + qcA)*Nn;
    const float* bB = g_bias + ((size_t)h*Nn + qcB)*Nn;

    // Q fragments (half2, scale*log2e folded by qkv)
    unsigned aq[2][4];
    {
        const __half* qp = g_q + (size_t)bh*Nn*HD;
        #pragma unroll
        for (int kc = 0; kc < 2; kc++) {
            aq[kc][0] = *(const unsigned*)&qp[(size_t)qcA*HD + kc*16 + 2*t];
            aq[kc][1] = *(const unsigned*)&qp[(size_t)qcB*HD + kc*16 + 2*t];
            aq[kc][2] = *(const unsigned*)&qp[(size_t)qcA*HD + kc*16 + 2*t + 8];
            aq[kc][3] = *(const unsigned*)&qp[(size_t)qcB*HD + kc*16 + 2*t + 8];
        }
    }

    const int kkey = tid >> 2, kd8 = (tid & 3) << 3;
    const int vd = tid >> 3, vk8 = (tid & 7) << 3;
    auto issue = [&](int tile) {
        int key0 = tile * 64, bf = tile & 1;
        cpasync16(&Ks[bf][kkey*40 + kd8], &g_k[((size_t)bh*Nn + key0 + kkey)*HD + kd8]);
        cpasync16(&Vs[bf][vd*72 + vk8],   &g_vT[((size_t)bh*HD + vd)*VROW + key0 + vk8]);
        CP_COMMIT();
    };

    float lA = 0.f, lB = 0.f;
    float o[4][4];
    #pragma unroll
    for (int i = 0; i < 4; i++)
        #pragma unroll
        for (int r = 0; r < 4; r++) o[i][r] = 0.f;

    issue(0);
    for (int tile = 0; tile < 12; tile++) {
        CP_WAIT(0);
        __syncthreads();
        if (tile + 1 < 12) issue(tile + 1);

        const __half* K = Ks[tile & 1];
        const __half* V = Vs[tile & 1];
        const int key0 = tile * 64;
        const bool lastTile = (key0 + 64 > Nn);

        // 4 independent pair-units: S (2 n-frags) -> ex2 -> PV k-chunk np
        #pragma unroll
        for (int np = 0; np < 4; np++) {
            const int nt0 = 2*np, nt1 = 2*np + 1;
            float c0[4] = {0.f, 0.f, 0.f, 0.f};
            float c1[4] = {0.f, 0.f, 0.f, 0.f};
            #pragma unroll
            for (int kc = 0; kc < 2; kc++) {
                unsigned kb0 = *(const unsigned*)&K[(nt0*8 + g)*40 + kc*16 + 2*t];
                unsigned kb1 = *(const unsigned*)&K[(nt0*8 + g)*40 + kc*16 + 2*t + 8];
                mma16816(c0, aq[kc], kb0, kb1);
                unsigned kb2 = *(const unsigned*)&K[(nt1*8 + g)*40 + kc*16 + 2*t];
                unsigned kb3 = *(const unsigned*)&K[(nt1*8 + g)*40 + kc*16 + 2*t + 8];
                mma16816(c1, aq[kc], kb2, kb3);
            }
            int j0 = key0 + nt0*8 + 2*t;
            int j1 = key0 + nt1*8 + 2*t;
            float2 vbA0 = *(const float2*)&bA[j0];
            float2 vbB0 = *(const float2*)&bB[j0];
            float2 vbA1 = *(const float2*)&bA[j1];
            float2 vbB1 = *(const float2*)&bB[j1];
            float p00 = ex2f(c0[0] + vbA0.x);
            float p01 = ex2f(c0[1] + vbA0.y);
            float p02 = ex2f(c0[2] + vbB0.x);
            float p03 = ex2f(c0[3] + vbB0.y);
            float p10 = ex2f(c1[0] + vbA1.x);
            float p11 = ex2f(c1[1] + vbA1.y);
            float p12 = ex2f(c1[2] + vbB1.x);
            float p13 = ex2f(c1[3] + vbB1.y);
            if (lastTile) {
                if (j0     >= Nn) { p00 = 0.f; p02 = 0.f; }
                if (j0 + 1 >= Nn) { p01 = 0.f; p03 = 0.f; }
                if (j1     >= Nn) { p10 = 0.f; p12 = 0.f; }
                if (j1 + 1 >= Nn) { p11 = 0.f; p13 = 0.f; }
            }
            lA += p00 + p01 + p10 + p11;
            lB += p02 + p03 + p12 + p13;
            // A-fragment for PV k-chunk np (rows g / g+8, k = pair keys)
            unsigned a[4] = { h2u(__floats2half2_rn(p00, p01)),
                              h2u(__floats2half2_rn(p02, p03)),
                              h2u(__floats2half2_rn(p10, p11)),
                              h2u(__floats2half2_rn(p12, p13)) };
            #pragma unroll
            for (int nt2 = 0; nt2 < 4; nt2++) {
                unsigned b0 = *(const unsigned*)&V[(nt2*8 + g)*72 + np*16 + 2*t];
                unsigned b1 = *(const unsigned*)&V[(nt2*8 + g)*72 + np*16 + 2*t + 8];
                mma16816(o[nt2], a, b0, b1);
            }
        }
    }

    // deferred l reduction (single pass at the end)
    lA += __shfl_xor_sync(0xffffffffu, lA, 1);
    lA += __shfl_xor_sync(0xffffffffu, lA, 2);
    lB += __shfl_xor_sync(0xffffffffu, lB, 1);
    lB += __shfl_xor_sync(0xffffffffu, lB, 2);

    float invA = 1.f / lA, invB = 1.f / lB;
    #pragma unroll
    for (int nt2 = 0; nt2 < 4; nt2++) {
        int d = h*HD + nt2*8 + 2*t;
        if (qrA < Nn) {
            __half2 hv = __floats2half2_rn(o[nt2][0]*invA, o[nt2][1]*invA);
            *(__half2*)&g_ao[((size_t)b*Nn + qrA)*Cc + d] = hv;
        }
        if (qrB < Nn) {
            __half2 hv = __floats2half2_rn(o[nt2][2]*invB, o[nt2][3]*invB);
            *(__half2*)&g_ao[((size_t)b*Nn + qrB)*Cc + d] = hv;
        }
    }
}

// ===========================================================================
// Projection (fp16 mma + ldmatrix + 3-stage cp.async): ao_h @ Wproj_h + b
// ===========================================================================
__global__ __launch_bounds__(256, 2) void proj_kernel(
    const float* __restrict__ bias, float* __restrict__ out)
{
    extern __shared__ __half sm[];
    __half* AsB = sm;
    __half* BsB = sm + 3*A_STG;

    const int tid = threadIdx.x;
    const int lane = tid & 31, w = tid >> 5;
    const int g = lane >> 2, t = lane & 3;
    const int m0 = blockIdx.x * 128, n0 = blockIdx.y * 128;
    const int wm = (w >> 2) * 64, wn = (w & 3) * 32;

    const int ar = tid >> 2, ak8 = (tid & 3) << 3;
    const int br = tid >> 4, bn8 = (tid & 15) << 3;
    const int mi = lane >> 3, rr = lane & 7;
    const int a_ro = ((mi & 1) << 3) + rr, a_co = (mi >> 1) << 3;

    float c[4][4][4];
    #pragma unroll
    for (int i = 0; i < 4; i++)
        #pragma unroll
        for (int j = 0; j < 4; j++)
            #pragma unroll
            for (int r = 0; r < 4; r++) c[i][j][r] = 0.f;

    auto loadStage = [&](int kb, int stg) {
        __half* A = AsB + stg*A_STG;
        __half* B = BsB + stg*B_STG;
        #pragma unroll
        for (int s = 0; s < 2; s++) {
            int row = ar + s*64;
            int gm = min(m0 + row, Mrows - 1);
            cpasync16(&A[row*40 + ak8], &g_ao[(size_t)gm*Cc + kb + ak8]);
        }
        #pragma unroll
        for (int s = 0; s < 2; s++) {
            int r = br + s*16;
            cpasync16(&B[r*136 + bn8], &g_wph[(size_t)(kb + r)*Cc + n0 + bn8]);
        }
        CP_COMMIT();
    };

    loadStage(0, 0);
    loadStage(32, 1);
    int st = 0, ld = 2;
    for (int s = 0; s < 16; s++) {
        if (s < 15) { CP_WAIT(1); } else { CP_WAIT(0); }
        __syncthreads();
        if (s + 2 < 16) loadStage((s + 2)*32, ld);

        const __half* A = AsB + st*A_STG;
        const __half* B = BsB + st*B_STG;
        #pragma unroll
        for (int kc = 0; kc < 2; kc++) {
            unsigned a[4][4], b[2][4];
            #pragma unroll
            for (int mt = 0; mt < 4; mt++) {
                unsigned addr = (unsigned)__cvta_generic_to_shared(
                    &A[(wm + mt*16 + a_ro)*40 + kc*16 + a_co]);
                ldsm4(a[mt], addr);
            }
            #pragma unroll
            for (int ntp = 0; ntp < 2; ntp++) {
                unsigned addr = (unsigned)__cvta_generic_to_shared(
                    &B[(kc*16 + a_ro)*136 + wn + ntp*16 + a_co]);
                ldsm4t(b[ntp], addr);
            }
            #pragma unroll
            for (int mt = 0; mt < 4; mt++)
                #pragma unroll
                for (int nt = 0; nt < 4; nt++) {
                    unsigned b0 = (nt & 1) ? b[nt>>1][2] : b[nt>>1][0];
                    unsigned b1 = (nt & 1) ? b[nt>>1][3] : b[nt>>1][1];
                    mma16816(c[mt][nt], a[mt], b0, b1);
                }
        }
        st = (st == 2) ? 0 : st + 1;
        ld = (ld == 2) ? 0 : ld + 1;
    }

    #pragma unroll
    for (int mt = 0; mt < 4; mt++) {
        #pragma unroll
        for (int nt = 0; nt < 4; nt++) {
            int n = n0 + wn + nt*8 + 2*t;
            float b0 = bias[n], b1 = bias[n + 1];
            #pragma unroll
            for (int half_ = 0; half_ < 2; half_++) {
                int mrow = m0 + wm + mt*16 + g + half_*8;
                if (mrow >= Mrows) continue;
                float v0 = c[mt][nt][half_*2 + 0] + b0;
                float v1 = c[mt][nt][half_*2 + 1] + b1;
                *(float2*)&out[(size_t)mrow*Cc + n] = make_float2(v0, v1);
            }
        }
    }
}

// ===========================================================================
extern "C" void kernel_launch(void* const* d_in, const int* in_sizes, int n_in,
                              void* d_out, int out_size)
{
    const float* x            = (const float*)d_in[0];
    const float* Wqkv         = (const float*)d_in[1];
    const float* bqkv         = (const float*)d_in[2];
    const float* Wproj        = (const float*)d_in[3];
    const float* bproj        = (const float*)d_in[4];
    const float* bt_target    = (const float*)d_in[5];
    const float* bt_temp      = (const float*)d_in[6];
    const float* tmp_tgt_tab  = (const float*)d_in[7];
    const float* tgt_tmp_tab  = (const float*)d_in[8];
    const float* tmp_tgt_line = (const float*)d_in[9];
    const float* tgt_tmp_line = (const float*)d_in[10];
    float* out = (float*)d_out;

    cudaFuncSetAttribute(qkv_kernel,  cudaFuncAttributeMaxDynamicSharedMemorySize, SMEM_GEMM);
    cudaFuncSetAttribute(proj_kernel, cudaFuncAttributeMaxDynamicSharedMemorySize, SMEM_GEMM);

    prep_kernel<<<dim3(Nn, 17), 256>>>(x, Wqkv, Wproj,
        bt_target, bt_temp, tmp_tgt_tab, tgt_tmp_tab, tmp_tgt_line, tgt_tmp_line);
    qkv_kernel<<<dim3(93, 12), 256, SMEM_GEMM>>>(bqkv);
    attn_kernel<<<dim3(6, 256), 256>>>();
    proj_kernel<<<dim3(93, 4), 256, SMEM_GEMM>>>(bproj, out);
}

// round 15
// speedup vs baseline: 1.2352x; 1.0094x over previous
#include <cuda_runtime.h>
#include <cuda_fp16.h>

#define Bsz 16
#define Nn  740
#define Hh  16
#define HD  32
#define Cc  512
#define N3  1536
#define Mrows (Bsz*Nn)            // 11840
#define SCALE 0.1767766952966369f // 1/sqrt(32)
#define LOG2E 1.4426950408889634f
#define QSCALE (SCALE*LOG2E)      // exp(x) == ex2(x*log2e)
#define VROW 744                  // padded g_vT row (16B-aligned)

// ---------------- static device scratch (no allocations allowed) ----------
__device__ __align__(128) __half g_xh [(size_t)Mrows*Cc];
__device__ __align__(128) __half g_wqh[(size_t)Cc*N3];
__device__ __align__(128) __half g_wph[(size_t)Cc*Cc];
__device__ __align__(128) __half g_q  [(size_t)Bsz*Hh*Nn*HD + 64];
__device__ __align__(128) __half g_k  [(size_t)Bsz*Hh*Nn*HD + 32768]; // + tail pad
__device__ __align__(128) __half g_vT [(size_t)Bsz*Hh*HD*VROW + 1024];
__device__ __align__(128) __half g_ao [(size_t)Mrows*Cc];
__device__ float g_bias[(size_t)Hh*Nn*Nn + 64];   // pre-multiplied by LOG2E

// ---------------- helpers --------------------------------------------------
__device__ __forceinline__ void mma16816(float* c, const unsigned* a,
                                         unsigned b0, unsigned b1) {
    asm volatile(
        "mma.sync.aligned.m16n8k16.row.col.f32.f16.f16.f32 "
        "{%0,%1,%2,%3}, {%4,%5,%6,%7}, {%8,%9}, {%0,%1,%2,%3};\n"
        : "+f"(c[0]), "+f"(c[1]), "+f"(c[2]), "+f"(c[3])
        : "r"(a[0]), "r"(a[1]), "r"(a[2]), "r"(a[3]), "r"(b0), "r"(b1));
}
__device__ __forceinline__ void ldsm4(unsigned* r, unsigned addr) {
    asm volatile("ldmatrix.sync.aligned.m8n8.x4.shared.b16 {%0,%1,%2,%3}, [%4];\n"
                 : "=r"(r[0]), "=r"(r[1]), "=r"(r[2]), "=r"(r[3]) : "r"(addr));
}
__device__ __forceinline__ void ldsm4t(unsigned* r, unsigned addr) {
    asm volatile("ldmatrix.sync.aligned.m8n8.x4.trans.shared.b16 {%0,%1,%2,%3}, [%4];\n"
                 : "=r"(r[0]), "=r"(r[1]), "=r"(r[2]), "=r"(r[3]) : "r"(addr));
}
__device__ __forceinline__ void cpasync16(void* sdst, const void* gsrc) {
    unsigned sa = (unsigned)__cvta_generic_to_shared(sdst);
    asm volatile("cp.async.cg.shared.global [%0], [%1], 16;\n" :: "r"(sa), "l"(gsrc));
}
#define CP_COMMIT() asm volatile("cp.async.commit_group;\n")
#define CP_WAIT(N)  asm volatile("cp.async.wait_group %0;\n" :: "n"(N))
__device__ __forceinline__ unsigned h2u(__half2 h) { return *(unsigned*)&h; }
__device__ __forceinline__ float ex2f(float x) {
    float y; asm("ex2.approx.ftz.f32 %0, %1;" : "=f"(y) : "f"(x)); return y;
}

// GEMM stage sizes in halves: A [128][40], B [32][136]
#define A_STG (128*40)
#define B_STG (32*136)
#define SMEM_GEMM (3*(A_STG + B_STG)*2)

// ===========================================================================
// prep: grid.y < 16 -> bias rows (h = blockIdx.y); grid.y == 16 -> fp32->fp16
// conversion of x / W_qkv / W_proj (grid-stride over blockIdx.x).
// ===========================================================================
__global__ __launch_bounds__(256) void prep_kernel(
    const float* __restrict__ x, const float* __restrict__ wq,
    const float* __restrict__ wp,
    const float* __restrict__ bt_target, const float* __restrict__ bt_temp,
    const float* __restrict__ tmp_tgt_tab, const float* __restrict__ tgt_tmp_tab,
    const float* __restrict__ tmp_tgt_line, const float* __restrict__ tgt_tmp_line)
{
    if (blockIdx.y == 16) {
        const int XN = Mrows*Cc/4, QN = Cc*N3/4, PN = Cc*Cc/4;
        const int total = XN + QN + PN;
        const int stride = gridDim.x * blockDim.x;
        for (int i = blockIdx.x*blockDim.x + threadIdx.x; i < total; i += stride) {
            const float4* src; __half* dst; int j = i;
            if (j < XN)           { src = (const float4*)x;  dst = g_xh; }
            else if (j < XN + QN) { j -= XN; src = (const float4*)wq; dst = g_wqh; }
            else                  { j -= XN + QN; src = (const float4*)wp; dst = g_wph; }
            float4 f = src[j];
            __half2 h0 = __floats2half2_rn(f.x, f.y);
            __half2 h1 = __floats2half2_rn(f.z, f.w);
            *(uint2*)&dst[(size_t)j*4] = make_uint2(h2u(h0), h2u(h1));
        }
        return;
    }
    const int i = blockIdx.x, h = blockIdx.y;
    const bool tmpR = i < 256;
    int r0, r1; float rowline;
    if (tmpR) { r0 = i >> 4; r1 = i & 15; rowline = tgt_tmp_tab[h*256 + i]; }
    else      { int a = i - 256; r0 = a/22; r1 = a%22; rowline = tmp_tgt_tab[h*484 + a]; }
    float* dst = g_bias + ((size_t)h*Nn + i)*Nn;
    for (int j = threadIdx.x; j < Nn; j += 256) {
        float bv;
        if (j < 256) {
            if (tmpR) {
                int idx = (r0 - (j >> 4) + 15)*31 + (r1 - (j & 15) + 15);
                bv = bt_temp[idx*Hh + h];
            } else bv = rowline + tmp_tgt_line[h*256 + j];
        } else {
            int cc = j - 256;
            if (tmpR) bv = rowline + tgt_tmp_line[h*484 + cc];
            else {
                int idx = (r0 - cc/22 + 21)*43 + (r1 - cc%22 + 21);
                bv = bt_target[idx*Hh + h];
            }
        }
        dst[j] = bv * LOG2E;
    }
}

// ===========================================================================
// QKV GEMM (fp16 mma + ldmatrix + 3-stage cp.async): x_h @ Wqkv_h + b
//   -> q (scaled*log2e, [n,d]), k ([n,d]), vT ([d,n])
// ===========================================================================
__global__ __launch_bounds__(256, 2) void qkv_kernel(const float* __restrict__ bias)
{
    extern __shared__ __half sm[];
    __half* AsB = sm;
    __half* BsB = sm + 3*A_STG;

    const int tid = threadIdx.x;
    const int lane = tid & 31, w = tid >> 5;
    const int g = lane >> 2, t = lane & 3;
    const int m0 = blockIdx.x * 128, n0 = blockIdx.y * 128;
    const int wm = (w >> 2) * 64, wn = (w & 3) * 32;

    const int ar = tid >> 2, ak8 = (tid & 3) << 3;
    const int br = tid >> 4, bn8 = (tid & 15) << 3;
    const int mi = lane >> 3, rr = lane & 7;
    const int a_ro = ((mi & 1) << 3) + rr, a_co = (mi >> 1) << 3;

    float c[4][4][4];
    #pragma unroll
    for (int i = 0; i < 4; i++)
        #pragma unroll
        for (int j = 0; j < 4; j++)
            #pragma unroll
            for (int r = 0; r < 4; r++) c[i][j][r] = 0.f;

    auto loadStage = [&](int kb, int stg) {
        __half* A = AsB + stg*A_STG;
        __half* B = BsB + stg*B_STG;
        #pragma unroll
        for (int s = 0; s < 2; s++) {
            int row = ar + s*64;
            int gm = min(m0 + row, Mrows - 1);
            cpasync16(&A[row*40 + ak8], &g_xh[(size_t)gm*Cc + kb + ak8]);
        }
        #pragma unroll
        for (int s = 0; s < 2; s++) {
            int r = br + s*16;
            cpasync16(&B[r*136 + bn8], &g_wqh[(size_t)(kb + r)*N3 + n0 + bn8]);
        }
        CP_COMMIT();
    };

    loadStage(0, 0);
    loadStage(32, 1);
    int st = 0, ld = 2;
    for (int s = 0; s < 16; s++) {
        if (s < 15) { CP_WAIT(1); } else { CP_WAIT(0); }
        __syncthreads();
        if (s + 2 < 16) loadStage((s + 2)*32, ld);

        const __half* A = AsB + st*A_STG;
        const __half* B = BsB + st*B_STG;
        #pragma unroll
        for (int kc = 0; kc < 2; kc++) {
            unsigned a[4][4], b[2][4];
            #pragma unroll
            for (int mt = 0; mt < 4; mt++) {
                unsigned addr = (unsigned)__cvta_generic_to_shared(
                    &A[(wm + mt*16 + a_ro)*40 + kc*16 + a_co]);
                ldsm4(a[mt], addr);
            }
            #pragma unroll
            for (int ntp = 0; ntp < 2; ntp++) {
                unsigned addr = (unsigned)__cvta_generic_to_shared(
                    &B[(kc*16 + a_ro)*136 + wn + ntp*16 + a_co]);
                ldsm4t(b[ntp], addr);
            }
            #pragma unroll
            for (int mt = 0; mt < 4; mt++)
                #pragma unroll
                for (int nt = 0; nt < 4; nt++) {
                    unsigned b0 = (nt & 1) ? b[nt>>1][2] : b[nt>>1][0];
                    unsigned b1 = (nt & 1) ? b[nt>>1][3] : b[nt>>1][1];
                    mma16816(c[mt][nt], a[mt], b0, b1);
                }
        }
        st = (st == 2) ? 0 : st + 1;
        ld = (ld == 2) ? 0 : ld + 1;
    }

    const int sec = n0 >> 9;
    #pragma unroll
    for (int mt = 0; mt < 4; mt++) {
        #pragma unroll
        for (int nt = 0; nt < 4; nt++) {
            int n = n0 + wn + nt*8 + 2*t;
            float b0 = bias[n], b1 = bias[n + 1];
            int h = (n >> 5) & 15, d = n & 31;
            #pragma unroll
            for (int half_ = 0; half_ < 2; half_++) {
                int mrow = m0 + wm + mt*16 + g + half_*8;
                if (mrow >= Mrows) continue;
                float v0 = c[mt][nt][half_*2 + 0] + b0;
                float v1 = c[mt][nt][half_*2 + 1] + b1;
                int b_ = mrow / Nn, nr = mrow % Nn;
                size_t bh = (size_t)b_*Hh + h;
                if (sec == 0) {
                    __half2 hv = __floats2half2_rn(v0*QSCALE, v1*QSCALE);
                    *(__half2*)&g_q[(bh*Nn + nr)*HD + d] = hv;
                } else if (sec == 1) {
                    __half2 hv = __floats2half2_rn(v0, v1);
                    *(__half2*)&g_k[(bh*Nn + nr)*HD + d] = hv;
                } else {
                    g_vT[(bh*HD + d    )*VROW + nr] = __float2half(v0);
                    g_vT[(bh*HD + d + 1)*VROW + nr] = __float2half(v1);
                }
            }
        }
    }
}

// ===========================================================================
// Fused flash attention (R11 pair-unit structure), 128-key tiles:
// half the barriers / pipeline refills of the 64-key version.
// ===========================================================================
__global__ __launch_bounds__(256) void attn_kernel()
{
    __shared__ __half Ks[2][128*40];   // [key][d] (pad 40)
    __shared__ __half Vs[2][32*136];   // [d][key] (pad 136)
    const int tid = threadIdx.x;
    const int lane = tid & 31, w = tid >> 5;
    const int g = lane >> 2, t = lane & 3;
    const int qbase = blockIdx.x * 128;
    const int bh = blockIdx.y;
    const int b = bh >> 4, h = bh & 15;

    const int qrA = qbase + w*16 + g;
    const int qrB = qrA + 8;
    const int qcA = min(qrA, Nn - 1), qcB = min(qrB, Nn - 1);

    const float* bA = g_bias + ((size_t)h*Nn + qcA)*Nn;
    const float* bB = g_bias + ((size_t)h*Nn + qcB)*Nn;

    // Q fragments (half2, scale*log2e folded by qkv)
    unsigned aq[2][4];
    {
        const __half* qp = g_q + (size_t)bh*Nn*HD;
        #pragma unroll
        for (int kc = 0; kc < 2; kc++) {
            aq[kc][0] = *(const unsigned*)&qp[(size_t)qcA*HD + kc*16 + 2*t];
            aq[kc][1] = *(const unsigned*)&qp[(size_t)qcB*HD + kc*16 + 2*t];
            aq[kc][2] = *(const unsigned*)&qp[(size_t)qcA*HD + kc*16 + 2*t + 8];
            aq[kc][3] = *(const unsigned*)&qp[(size_t)qcB*HD + kc*16 + 2*t + 8];
        }
    }

    const int kkey = tid >> 2, kd8 = (tid & 3) << 3;   // K: rows kkey, kkey+64
    const int vd = tid >> 3, vk8 = (tid & 7) << 3;     // V: cols vk8, vk8+64
    auto issue = [&](int tile) {
        int key0 = tile * 128, bf = tile & 1;
        cpasync16(&Ks[bf][kkey*40 + kd8],
                  &g_k[((size_t)bh*Nn + key0 + kkey)*HD + kd8]);
        cpasync16(&Ks[bf][(kkey + 64)*40 + kd8],
                  &g_k[((size_t)bh*Nn + key0 + kkey + 64)*HD + kd8]);
        cpasync16(&Vs[bf][vd*136 + vk8],
                  &g_vT[((size_t)bh*HD + vd)*VROW + key0 + vk8]);
        cpasync16(&Vs[bf][vd*136 + vk8 + 64],
                  &g_vT[((size_t)bh*HD + vd)*VROW + key0 + vk8 + 64]);
        CP_COMMIT();
    };

    float lA = 0.f, lB = 0.f;
    float o[4][4];
    #pragma unroll
    for (int i = 0; i < 4; i++)
        #pragma unroll
        for (int r = 0; r < 4; r++) o[i][r] = 0.f;

    issue(0);
    for (int tile = 0; tile < 6; tile++) {
        CP_WAIT(0);
        __syncthreads();
        if (tile + 1 < 6) issue(tile + 1);

        const __half* K = Ks[tile & 1];
        const __half* V = Vs[tile & 1];
        const int key0 = tile * 128;
        const bool lastTile = (key0 + 128 > Nn);

        // 8 independent pair-units: S (2 n-frags) -> ex2 -> PV k-chunk np
        #pragma unroll
        for (int np = 0; np < 8; np++) {
            const int nt0 = 2*np, nt1 = 2*np + 1;
            float c0[4] = {0.f, 0.f, 0.f, 0.f};
            float c1[4] = {0.f, 0.f, 0.f, 0.f};
            #pragma unroll
            for (int kc = 0; kc < 2; kc++) {
                unsigned kb0 = *(const unsigned*)&K[(nt0*8 + g)*40 + kc*16 + 2*t];
                unsigned kb1 = *(const unsigned*)&K[(nt0*8 + g)*40 + kc*16 + 2*t + 8];
                mma16816(c0, aq[kc], kb0, kb1);
                unsigned kb2 = *(const unsigned*)&K[(nt1*8 + g)*40 + kc*16 + 2*t];
                unsigned kb3 = *(const unsigned*)&K[(nt1*8 + g)*40 + kc*16 + 2*t + 8];
                mma16816(c1, aq[kc], kb2, kb3);
            }
            int j0 = key0 + nt0*8 + 2*t;
            int j1 = key0 + nt1*8 + 2*t;
            float2 vbA0 = *(const float2*)&bA[j0];
            float2 vbB0 = *(const float2*)&bB[j0];
            float2 vbA1 = *(const float2*)&bA[j1];
            float2 vbB1 = *(const float2*)&bB[j1];
            float p00 = ex2f(c0[0] + vbA0.x);
            float p01 = ex2f(c0[1] + vbA0.y);
            float p02 = ex2f(c0[2] + vbB0.x);
            float p03 = ex2f(c0[3] + vbB0.y);
            float p10 = ex2f(c1[0] + vbA1.x);
            float p11 = ex2f(c1[1] + vbA1.y);
            float p12 = ex2f(c1[2] + vbB1.x);
            float p13 = ex2f(c1[3] + vbB1.y);
            if (lastTile) {
                if (j0     >= Nn) { p00 = 0.f; p02 = 0.f; }
                if (j0 + 1 >= Nn) { p01 = 0.f; p03 = 0.f; }
                if (j1     >= Nn) { p10 = 0.f; p12 = 0.f; }
                if (j1 + 1 >= Nn) { p11 = 0.f; p13 = 0.f; }
            }
            lA += p00 + p01 + p10 + p11;
            lB += p02 + p03 + p12 + p13;
            // A-fragment for PV k-chunk np (rows g / g+8, k = pair keys)
            unsigned a[4] = { h2u(__floats2half2_rn(p00, p01)),
                              h2u(__floats2half2_rn(p02, p03)),
                              h2u(__floats2half2_rn(p10, p11)),
                              h2u(__floats2half2_rn(p12, p13)) };
            #pragma unroll
            for (int nt2 = 0; nt2 < 4; nt2++) {
                unsigned b0 = *(const unsigned*)&V[(nt2*8 + g)*136 + np*16 + 2*t];
                unsigned b1 = *(const unsigned*)&V[(nt2*8 + g)*136 + np*16 + 2*t + 8];
                mma16816(o[nt2], a, b0, b1);
            }
        }
    }

    // deferred l reduction (single pass at the end)
    lA += __shfl_xor_sync(0xffffffffu, lA, 1);
    lA += __shfl_xor_sync(0xffffffffu, lA, 2);
    lB += __shfl_xor_sync(0xffffffffu, lB, 1);
    lB += __shfl_xor_sync(0xffffffffu, lB, 2);

    float invA = 1.f / lA, invB = 1.f / lB;
    #pragma unroll
    for (int nt2 = 0; nt2 < 4; nt2++) {
        int d = h*HD + nt2*8 + 2*t;
        if (qrA < Nn) {
            __half2 hv = __floats2half2_rn(o[nt2][0]*invA, o[nt2][1]*invA);
            *(__half2*)&g_ao[((size_t)b*Nn + qrA)*Cc + d] = hv;
        }
        if (qrB < Nn) {
            __half2 hv = __floats2half2_rn(o[nt2][2]*invB, o[nt2][3]*invB);
            *(__half2*)&g_ao[((size_t)b*Nn + qrB)*Cc + d] = hv;
        }
    }
}

// ===========================================================================
// Projection (fp16 mma + ldmatrix + 3-stage cp.async): ao_h @ Wproj_h + b
// ===========================================================================
__global__ __launch_bounds__(256, 2) void proj_kernel(
    const float* __restrict__ bias, float* __restrict__ out)
{
    extern __shared__ __half sm[];
    __half* AsB = sm;
    __half* BsB = sm + 3*A_STG;

    const int tid = threadIdx.x;
    const int lane = tid & 31, w = tid >> 5;
    const int g = lane >> 2, t = lane & 3;
    const int m0 = blockIdx.x * 128, n0 = blockIdx.y * 128;
    const int wm = (w >> 2) * 64, wn = (w & 3) * 32;

    const int ar = tid >> 2, ak8 = (tid & 3) << 3;
    const int br = tid >> 4, bn8 = (tid & 15) << 3;
    const int mi = lane >> 3, rr = lane & 7;
    const int a_ro = ((mi & 1) << 3) + rr, a_co = (mi >> 1) << 3;

    float c[4][4][4];
    #pragma unroll
    for (int i = 0; i < 4; i++)
        #pragma unroll
        for (int j = 0; j < 4; j++)
            #pragma unroll
            for (int r = 0; r < 4; r++) c[i][j][r] = 0.f;

    auto loadStage = [&](int kb, int stg) {
        __half* A = AsB + stg*A_STG;
        __half* B = BsB + stg*B_STG;
        #pragma unroll
        for (int s = 0; s < 2; s++) {
            int row = ar + s*64;
            int gm = min(m0 + row, Mrows - 1);
            cpasync16(&A[row*40 + ak8], &g_ao[(size_t)gm*Cc + kb + ak8]);
        }
        #pragma unroll
        for (int s = 0; s < 2; s++) {
            int r = br + s*16;
            cpasync16(&B[r*136 + bn8], &g_wph[(size_t)(kb + r)*Cc + n0 + bn8]);
        }
        CP_COMMIT();
    };

    loadStage(0, 0);
    loadStage(32, 1);
    int st = 0, ld = 2;
    for (int s = 0; s < 16; s++) {
        if (s < 15) { CP_WAIT(1); } else { CP_WAIT(0); }
        __syncthreads();
        if (s + 2 < 16) loadStage((s + 2)*32, ld);

        const __half* A = AsB + st*A_STG;
        const __half* B = BsB + st*B_STG;
        #pragma unroll
        for (int kc = 0; kc < 2; kc++) {
            unsigned a[4][4], b[2][4];
            #pragma unroll
            for (int mt = 0; mt < 4; mt++) {
                unsigned addr = (unsigned)__cvta_generic_to_shared(
                    &A[(wm + mt*16 + a_ro)*40 + kc*16 + a_co]);
                ldsm4(a[mt], addr);
            }
            #pragma unroll
            for (int ntp = 0; ntp < 2; ntp++) {
                unsigned addr = (unsigned)__cvta_generic_to_shared(
                    &B[(kc*16 + a_ro)*136 + wn + ntp*16 + a_co]);
                ldsm4t(b[ntp], addr);
            }
            #pragma unroll
            for (int mt = 0; mt < 4; mt++)
                #pragma unroll
                for (int nt = 0; nt < 4; nt++) {
                    unsigned b0 = (nt & 1) ? b[nt>>1][2] : b[nt>>1][0];
                    unsigned b1 = (nt & 1) ? b[nt>>1][3] : b[nt>>1][1];
                    mma16816(c[mt][nt], a[mt], b0, b1);
                }
        }
        st = (st == 2) ? 0 : st + 1;
        ld = (ld == 2) ? 0 : ld + 1;
    }

    #pragma unroll
    for (int mt = 0; mt < 4; mt++) {
        #pragma unroll
        for (int nt = 0; nt < 4; nt++) {
            int n = n0 + wn + nt*8 + 2*t;
            float b0 = bias[n], b1 = bias[n + 1];
            #pragma unroll
            for (int half_ = 0; half_ < 2; half_++) {
                int mrow = m0 + wm + mt*16 + g + half_*8;
                if (mrow >= Mrows) continue;
                float v0 = c[mt][nt][half_*2 + 0] + b0;
                float v1 = c[mt][nt][half_*2 + 1] + b1;
                *(float2*)&out[(size_t)mrow*Cc + n] = make_float2(v0, v1);
            }
        }
    }
}

// ===========================================================================
extern "C" void kernel_launch(void* const* d_in, const int* in_sizes, int n_in,
                              void* d_out, int out_size)
{
    const float* x            = (const float*)d_in[0];
    const float* Wqkv         = (const float*)d_in[1];
    const float* bqkv         = (const float*)d_in[2];
    const float* Wproj        = (const float*)d_in[3];
    const float* bproj        = (const float*)d_in[4];
    const float* bt_target    = (const float*)d_in[5];
    const float* bt_temp      = (const float*)d_in[6];
    const float* tmp_tgt_tab  = (const float*)d_in[7];
    const float* tgt_tmp_tab  = (const float*)d_in[8];
    const float* tmp_tgt_line = (const float*)d_in[9];
    const float* tgt_tmp_line = (const float*)d_in[10];
    float* out = (float*)d_out;

    cudaFuncSetAttribute(qkv_kernel,  cudaFuncAttributeMaxDynamicSharedMemorySize, SMEM_GEMM);
    cudaFuncSetAttribute(proj_kernel, cudaFuncAttributeMaxDynamicSharedMemorySize, SMEM_GEMM);

    prep_kernel<<<dim3(Nn, 17), 256>>>(x, Wqkv, Wproj,
        bt_target, bt_temp, tmp_tgt_tab, tgt_tmp_tab, tmp_tgt_line, tgt_tmp_line);
    qkv_kernel<<<dim3(93, 12), 256, SMEM_GEMM>>>(bqkv);
    attn_kernel<<<dim3(6, 256), 256>>>();
    proj_kernel<<<dim3(93, 4), 256, SMEM_GEMM>>>(bproj, out);
}